// round 11
// baseline (speedup 1.0000x reference)
#include <cuda_runtime.h>
#include <cuda_fp16.h>
#include <cstdint>

constexpr int B_ = 128;
constexpr int T_ = 1024;
constexpr int D_ = 512;
constexpr int H_ = 1024;
constexpr int G_ = 3 * H_;

constexpr int NT = 32;
constexpr int KS = 4;
constexpr int NB = NT * KS;           // 128

constexpr int IGN  = 64;
constexpr int IGNT = G_ / IGN;
constexpr int TG   = 4;

constexpr int R_WH = 0;
constexpr int R_WL = 49152;
constexpr int AB0  = 98304;
constexpr int AB1  = 131072;
constexpr int PRECV = 163840;
constexpr int R_SMEM = 212992;

constexpr int I_WH = 0;
constexpr int I_WL = 64 * 64 * 16;
constexpr int I_XH = 2 * 64 * 64 * 16;
constexpr int I_XL = I_XH + 128 * 16 * 16;
constexpr int I_SMEM = I_XL + 128 * 16 * 16;

__device__ __align__(128) __half g_x_hi[(size_t)B_ * T_ * D_];
__device__ __align__(128) __half g_x_lo[(size_t)B_ * T_ * D_];
__device__ __align__(128) __half g_whh_hi[(size_t)G_ * H_];
__device__ __align__(128) __half g_whh_lo[(size_t)G_ * H_];
__device__ __align__(128) __half g_wih_hi[(size_t)G_ * D_];
__device__ __align__(128) __half g_wih_lo[(size_t)G_ * D_];
__device__ float g_IG[(size_t)T_ * B_ * G_];
__device__ __align__(128) __half g_h_hi[2][B_ * H_];
__device__ __align__(128) __half g_h_lo[2][B_ * H_];
__device__ unsigned int g_Hf[NT][KS][32];

__device__ __forceinline__ uint32_t smem_u32(const void* p) {
    uint32_t a;
    asm("{ .reg .u64 t; cvta.to.shared.u64 t, %1; cvt.u32.u64 %0, t; }" : "=r"(a) : "l"(p));
    return a;
}
__device__ __forceinline__ void ldm4(uint32_t* r, uint32_t a) {
    asm volatile("ldmatrix.sync.aligned.m8n8.x4.shared.b16 {%0,%1,%2,%3}, [%4];"
                 : "=r"(r[0]), "=r"(r[1]), "=r"(r[2]), "=r"(r[3]) : "r"(a));
}
__device__ __forceinline__ void mma_f16(float* d, const uint32_t* a, uint32_t b0, uint32_t b1) {
    asm volatile(
        "mma.sync.aligned.m16n8k16.row.col.f32.f16.f16.f32 "
        "{%0,%1,%2,%3},{%4,%5,%6,%7},{%8,%9},{%0,%1,%2,%3};"
        : "+f"(d[0]), "+f"(d[1]), "+f"(d[2]), "+f"(d[3])
        : "r"(a[0]), "r"(a[1]), "r"(a[2]), "r"(a[3]), "r"(b0), "r"(b1));
}
__device__ __forceinline__ void cpa16(uint32_t s, const void* g) {
    asm volatile("cp.async.cg.shared.global [%0], [%1], 16;" :: "r"(s), "l"(g));
}
__device__ __forceinline__ void cp_commit() { asm volatile("cp.async.commit_group;" ::: "memory"); }
__device__ __forceinline__ void cp_wait0()  { asm volatile("cp.async.wait_group 0;" ::: "memory"); }
__device__ __forceinline__ void hsplit(float f, __half& hi, __half& lo) {
    hi = __float2half_rn(f);
    lo = __float2half_rn(f - __half2float(hi));
}
__device__ __forceinline__ void poll_ge(const unsigned int* p, unsigned int v) {
    unsigned int x;
    do {
        asm volatile("ld.acquire.gpu.global.u32 %0, [%1];" : "=r"(x) : "l"(p) : "memory");
    } while (x < v);
}
__device__ __forceinline__ void rel_st(unsigned int* p, unsigned int v) {
    asm volatile("st.release.gpu.global.u32 [%0], %1;" :: "l"(p), "r"(v) : "memory");
}
__device__ __forceinline__ void mbar_init(uint32_t a, uint32_t cnt) {
    asm volatile("mbarrier.init.shared.b64 [%0], %1;" :: "r"(a), "r"(cnt) : "memory");
}
__device__ __forceinline__ void mbar_expect(uint32_t a, uint32_t bytes) {
    asm volatile("mbarrier.arrive.expect_tx.shared.b64 _, [%0], %1;" :: "r"(a), "r"(bytes) : "memory");
}
__device__ __forceinline__ void mbar_wait(uint32_t a, uint32_t parity) {
    asm volatile(
        "{\n\t.reg .pred P;\n\tLAB_%=:\n\t"
        "mbarrier.try_wait.parity.shared.b64 P, [%0], %1;\n\t"
        "@!P bra LAB_%=;\n\t}"
        :: "r"(a), "r"(parity) : "memory");
}
__device__ __forceinline__ void mbar_wait_cl(uint32_t a, uint32_t parity) {
    asm volatile(
        "{\n\t.reg .pred P;\n\tLAB_%=:\n\t"
        "mbarrier.try_wait.parity.acquire.cluster.shared::cta.b64 P, [%0], %1;\n\t"
        "@!P bra LAB_%=;\n\t}"
        :: "r"(a), "r"(parity) : "memory");
}
// FIX (round 10 race): remote arrive must be RELEASE at CLUSTER scope so the
// preceding weak st.shared::cluster data stores are ordered for remote waiters.
__device__ __forceinline__ void mbar_arrive_rem(uint32_t raddr) {
    asm volatile("mbarrier.arrive.release.cluster.shared::cluster.b64 _, [%0];"
                 :: "r"(raddr) : "memory");
}
__device__ __forceinline__ void bulk_g2s(uint32_t smem, const void* g, uint32_t bytes, uint32_t mbar) {
    asm volatile(
        "cp.async.bulk.shared::cluster.global.mbarrier::complete_tx::bytes [%0], [%1], %2, [%3];"
        :: "r"(smem), "l"(g), "r"(bytes), "r"(mbar) : "memory");
}
__device__ __forceinline__ uint32_t mapa_u32(uint32_t laddr, uint32_t rank) {
    uint32_t r;
    asm("mapa.shared::cluster.u32 %0, %1, %2;" : "=r"(r) : "r"(laddr), "r"(rank));
    return r;
}
__device__ __forceinline__ void stc64(uint32_t a, float x, float y) {
    asm volatile("{ .reg .b64 v; mov.b64 v, {%1,%2}; st.shared::cluster.b64 [%0], v; }"
                 :: "r"(a), "f"(x), "f"(y) : "memory");
}
__device__ __forceinline__ void srdy_st(uint32_t a, unsigned v) {
    asm volatile("st.release.cta.shared.u32 [%0], %1;" :: "r"(a), "r"(v) : "memory");
}
__device__ __forceinline__ unsigned srdy_ld(uint32_t a) {
    unsigned v;
    asm volatile("ld.acquire.cta.shared.u32 %0, [%1];" : "=r"(v) : "r"(a) : "memory");
    return v;
}
__device__ __forceinline__ uint32_t hoff(int b, int j) {
    return ((uint32_t)(j >> 6) << 13) + ((uint32_t)b << 6)
         + ((uint32_t)(((j >> 3) & 7) ^ (b & 7)) << 3) + (uint32_t)(j & 7);
}

__global__ void init_kernel() {
    unsigned idx = blockIdx.x * blockDim.x + threadIdx.x;
    for (unsigned i = idx; i < (unsigned)(NT * KS * 32); i += gridDim.x * blockDim.x)
        (&g_Hf[0][0][0])[i] = 0u;
    for (unsigned i = idx; i < (unsigned)(B_ * H_); i += gridDim.x * blockDim.x) {
        g_h_hi[0][i] = __float2half(0.0f);
        g_h_lo[0][i] = __float2half(0.0f);
    }
}
__global__ void split_w(const float* __restrict__ whh, const float* __restrict__ wih) {
    size_t i = (size_t)blockIdx.x * blockDim.x + threadIdx.x;
    size_t nhh = (size_t)G_ * H_;
    if (i < nhh) {
        __half hi, lo; hsplit(whh[i], hi, lo);
        int ghrow = (int)(i >> 10), k = (int)(i & 1023);
        int gate = ghrow >> 10, hrow = ghrow & 1023;
        int nt = hrow >> 5, nc = gate * 32 + (hrow & 31);
        int ks = k >> 8, kk = k & 255;
        int swz = ((kk >> 3) & 7) ^ (nc & 7);
        size_t dst = (size_t)(nt * KS + ks) * 24576 + (kk >> 6) * 6144 + nc * 64 + swz * 8 + (kk & 7);
        g_whh_hi[dst] = hi; g_whh_lo[dst] = lo;
    } else if (i < nhh + (size_t)G_ * D_) {
        size_t j = i - nhh;
        __half hi, lo; hsplit(wih[j], hi, lo);
        g_wih_hi[j] = hi; g_wih_lo[j] = lo;
    }
}
__global__ void split_x(const float* __restrict__ x) {
    size_t i = (size_t)blockIdx.x * blockDim.x + threadIdx.x;
    size_t n2 = (size_t)B_ * T_ * D_ / 2;
    if (i < n2) {
        float2 v = reinterpret_cast<const float2*>(x)[i];
        __half h0, l0, h1, l1;
        hsplit(v.x, h0, l0); hsplit(v.y, h1, l1);
        reinterpret_cast<__half2*>(g_x_hi)[i] = __halves2half2(h0, h1);
        reinterpret_cast<__half2*>(g_x_lo)[i] = __halves2half2(l0, l1);
    }
}

// IG GEMM (proven, unchanged)
__global__ __launch_bounds__(256, 1) void ig_gemm(const float* __restrict__ bias) {
    extern __shared__ __align__(1024) char smem[];
    const uint32_t sb = smem_u32(smem);
    const int tid = threadIdx.x;
    const int lane = tid & 31, warp = tid >> 5;
    const int wm = warp >> 1, wn = warp & 1;
    const int g8 = lane >> 3, r8 = lane & 7;
    const int gq = lane >> 2, cq = lane & 3;
    const int n0 = blockIdx.x * IGN;

    int rowA[2], rowB[2];
    rowA[0] = wm * 32 + r8 + (g8 & 1) * 8; rowA[1] = rowA[0] + 16;
    rowB[0] = wn * 32 + r8 + (g8 >> 1) * 8; rowB[1] = rowB[0] + 16;
    const int cbA = g8 >> 1, cbB = g8 & 1;

    for (int idx = tid; idx < 64 * 64; idx += 256) {
        int row = idx >> 6, c = idx & 63;
        size_t src = (size_t)(n0 + row) * D_ + c * 8;
        uint32_t off = ((row * 64 + (c ^ (row & 7))) << 4);
        cpa16(sb + I_WH + off, g_wih_hi + src);
        cpa16(sb + I_WL + off, g_wih_lo + src);
    }
    cp_commit(); cp_wait0();
    __syncthreads();

    for (int tt = 0; tt < TG; tt++) {
        const int t = blockIdx.y * TG + tt;
        float acc[2][4][4];
#pragma unroll
        for (int i = 0; i < 2; i++)
#pragma unroll
            for (int j = 0; j < 4; j++)
#pragma unroll
                for (int q = 0; q < 4; q++) acc[i][j][q] = 0.0f;

        for (int kc = 0; kc < 4; kc++) {
            __syncthreads();
            for (int idx = tid; idx < 128 * 16; idx += 256) {
                int row = idx >> 4, c = idx & 15;
                size_t src = ((size_t)row * T_ + t) * D_ + kc * 128 + c * 8;
                uint32_t off = ((row * 16 + (c ^ (row & 7))) << 4);
                cpa16(sb + I_XH + off, g_x_hi + src);
                cpa16(sb + I_XL + off, g_x_lo + src);
            }
            cp_commit(); cp_wait0();
            __syncthreads();

#pragma unroll
            for (int kk = 0; kk < 8; kk++) {
                const int kk2 = kk * 2;
                uint32_t ah[2][4], al[2][4];
#pragma unroll
                for (int i = 0; i < 2; i++) {
                    uint32_t off = ((rowA[i] * 16 + ((kk2 + cbA) ^ (rowA[i] & 7))) << 4);
                    ldm4(ah[i], sb + I_XH + off);
                    ldm4(al[i], sb + I_XL + off);
                }
                const int kkc = kc * 16 + kk2;
                uint32_t bh[2][4], bl[2][4];
#pragma unroll
                for (int j = 0; j < 2; j++) {
                    uint32_t off = ((rowB[j] * 64 + ((kkc + cbB) ^ (rowB[j] & 7))) << 4);
                    ldm4(bh[j], sb + I_WH + off);
                    ldm4(bl[j], sb + I_WL + off);
                }
#pragma unroll
                for (int i = 0; i < 2; i++)
#pragma unroll
                    for (int j = 0; j < 2; j++) {
                        mma_f16(acc[i][2 * j],     ah[i], bh[j][0], bh[j][1]);
                        mma_f16(acc[i][2 * j + 1], ah[i], bh[j][2], bh[j][3]);
                        mma_f16(acc[i][2 * j],     ah[i], bl[j][0], bl[j][1]);
                        mma_f16(acc[i][2 * j + 1], ah[i], bl[j][2], bl[j][3]);
                        mma_f16(acc[i][2 * j],     al[i], bh[j][0], bh[j][1]);
                        mma_f16(acc[i][2 * j + 1], al[i], bh[j][2], bh[j][3]);
                    }
            }
        }

#pragma unroll
        for (int i = 0; i < 2; i++)
#pragma unroll
            for (int j = 0; j < 4; j++) {
                int row = wm * 32 + i * 16 + gq;
                int gcol = n0 + wn * 32 + j * 8 + 2 * cq;
                float b0 = __ldg(&bias[gcol]), b1 = __ldg(&bias[gcol + 1]);
                size_t o0 = ((size_t)t * B_ + row) * G_ + gcol;
                *reinterpret_cast<float2*>(&g_IG[o0]) =
                    make_float2(acc[i][j][0] + b0, acc[i][j][1] + b1);
                *reinterpret_cast<float2*>(&g_IG[o0 + (size_t)8 * G_]) =
                    make_float2(acc[i][j][2] + b0, acc[i][j][3] + b1);
            }
    }
}

// ---------------------------------------------------------------------------
// Persistent GRU recurrence: per-chunk early staging + mbar DSMEM exchange
// (round 10 + release.cluster fix)
// ---------------------------------------------------------------------------
__global__ __launch_bounds__(256, 1) __cluster_dims__(4, 1, 1)
void gru_persist(const float* __restrict__ bn) {
    extern __shared__ __align__(1024) char smem[];
    __shared__ __align__(16) unsigned long long s_bar[7];
    __shared__ unsigned s_rdy[2];
    const uint32_t sb = smem_u32(smem);
    uint32_t barC[4];
#pragma unroll
    for (int c = 0; c < 4; c++) barC[c] = smem_u32(&s_bar[c]);
    const uint32_t barW = smem_u32(&s_bar[4]);
    const uint32_t barF = smem_u32(&s_bar[5]);
    const uint32_t barE = smem_u32(&s_bar[6]);
    const uint32_t rdy0 = smem_u32(&s_rdy[0]);

    const int tid = threadIdx.x;
    const int lane = tid & 31, warp = tid >> 5;
    const int wm = warp >> 1, wn = warp & 1;
    const int g8 = lane >> 3, r8 = lane & 7;
    const int gq = lane >> 2, cq = lane & 3;

    uint32_t rank;
    asm("mov.u32 %0, %%cluster_ctarank;" : "=r"(rank));
    const int ks = (int)rank;
    const int nt = blockIdx.x >> 2;
    const int slab = nt * KS + ks;

    int rowA[2], rowB[3];
    rowA[0] = wm * 32 + r8 + (g8 & 1) * 8; rowA[1] = rowA[0] + 16;
    rowB[0] = wn * 48 + r8 + (g8 >> 1) * 8; rowB[1] = rowB[0] + 16; rowB[2] = rowB[0] + 32;
    const int cbA = g8 >> 1, cbB = g8 & 1;

    if (tid == 0) {
#pragma unroll
        for (int c = 0; c < 4; c++) mbar_init(barC[c], 1);
        mbar_init(barW, 1);
        mbar_init(barF, 8);
        mbar_init(barE, 4);
        s_rdy[0] = 0; s_rdy[1] = 0;
    }
    __syncthreads();
    asm volatile("barrier.cluster.arrive.aligned;" ::: "memory");
    asm volatile("barrier.cluster.wait.aligned;" ::: "memory");

    if (tid == 0) {
        mbar_expect(barW, 98304);
        bulk_g2s(sb + R_WH, g_whh_hi + (size_t)slab * 24576, 49152, barW);
        bulk_g2s(sb + R_WL, g_whh_lo + (size_t)slab * 24576, 49152, barW);
    }
    mbar_wait(barW, 0);
    __syncthreads();

    const int grl = tid >> 3;
    const int gc  = (tid & 7) * 4;
    const int hc  = nt * 32 + gc;
    const uint32_t rbase = mapa_u32(sb + PRECV + (uint32_t)ks * 12288, (uint32_t)wm);
    const uint32_t rfull = mapa_u32(barF, (uint32_t)wm);
    const uint32_t rempty = (tid < 4) ? mapa_u32(barE, (uint32_t)tid) : 0u;

    const unsigned int* myflag = &g_Hf[ks * 8 + 2 * (lane >> 3) + ((lane & 7) >> 2)][lane & 3][0];
    const unsigned grpmask = 0xFFu << ((lane >> 3) * 8);

    for (int t = 0; t < T_; t++) {
        const __half* hhi = g_h_hi[t & 1];
        const __half* hlo = g_h_lo[t & 1];

        if (warp == 0) {
            const int c = lane >> 3;
            poll_ge(myflag, (unsigned)t);
            __syncwarp(grpmask);
            if ((lane & 7) == 0) {
                if (c < 2) {
                    mbar_expect(barC[c], 32768);
                    uint32_t buf = sb + ((c & 1) ? AB1 : AB0);
                    bulk_g2s(buf,         hhi + (size_t)(ks * 4 + c) * 8192, 16384, barC[c]);
                    bulk_g2s(buf + 16384, hlo + (size_t)(ks * 4 + c) * 8192, 16384, barC[c]);
                } else {
                    srdy_st(rdy0 + (c - 2) * 4, (unsigned)(t + 1));
                }
            }
            __syncwarp();
        }

        float acc[2][6][4];
#pragma unroll
        for (int i = 0; i < 2; i++)
#pragma unroll
            for (int j = 0; j < 6; j++)
#pragma unroll
                for (int q = 0; q < 4; q++) acc[i][j][q] = 0.0f;

#pragma unroll
        for (int kc = 0; kc < 4; kc++) {
            const uint32_t buf = sb + ((kc & 1) ? AB1 : AB0);
            mbar_wait(barC[kc], (uint32_t)(t & 1));
#pragma unroll
            for (int kk = 0; kk < 4; kk++) {
                const int kk2 = kk * 2;
                uint32_t ah[2][4], al[2][4];
#pragma unroll
                for (int i = 0; i < 2; i++) {
                    int c = kk2 + cbA;
                    uint32_t off = ((uint32_t)rowA[i] << 7) + ((uint32_t)(c ^ (rowA[i] & 7)) << 4);
                    ldm4(ah[i], buf + off);
                    ldm4(al[i], buf + 16384 + off);
                }
                uint32_t bh[3][4], bl[3][4];
#pragma unroll
                for (int j = 0; j < 3; j++) {
                    int cg = kc * 8 + kk2 + cbB;
                    uint32_t off = (uint32_t)kc * 12288 + ((uint32_t)rowB[j] << 7)
                                 + ((uint32_t)((cg & 7) ^ (rowB[j] & 7)) << 4);
                    ldm4(bh[j], sb + R_WH + off);
                    ldm4(bl[j], sb + R_WL + off);
                }
#pragma unroll
                for (int i = 0; i < 2; i++)
#pragma unroll
                    for (int j = 0; j < 3; j++) {
                        mma_f16(acc[i][2 * j],     ah[i], bh[j][0], bh[j][1]);
                        mma_f16(acc[i][2 * j + 1], ah[i], bh[j][2], bh[j][3]);
                        mma_f16(acc[i][2 * j],     ah[i], bl[j][0], bl[j][1]);
                        mma_f16(acc[i][2 * j + 1], ah[i], bl[j][2], bl[j][3]);
                        mma_f16(acc[i][2 * j],     al[i], bh[j][0], bh[j][1]);
                        mma_f16(acc[i][2 * j + 1], al[i], bh[j][2], bh[j][3]);
                    }
            }
            if (kc < 2) {
                __syncthreads();
                if (tid == 0) {
                    while (srdy_ld(rdy0 + kc * 4) != (unsigned)(t + 1)) { }
                    mbar_expect(barC[kc + 2], 32768);
                    bulk_g2s(buf,         hhi + (size_t)(ks * 4 + kc + 2) * 8192, 16384, barC[kc + 2]);
                    bulk_g2s(buf + 16384, hlo + (size_t)(ks * 4 + kc + 2) * 8192, 16384, barC[kc + 2]);
                }
            }
        }

        const int grow = ks * 32 + grl;
        const float* ig_t = g_IG + ((size_t)t * B_ + grow) * G_;
        float4 igr = *reinterpret_cast<const float4*>(ig_t + hc);
        float4 igz = *reinterpret_cast<const float4*>(ig_t + H_ + hc);
        float4 ign = *reinterpret_cast<const float4*>(ig_t + 2 * H_ + hc);
        float4 bnv = *reinterpret_cast<const float4*>(bn + hc);
        uint32_t ho = hoff(grow, hc);
        uint2 rh = *reinterpret_cast<const uint2*>(hhi + ho);
        uint2 rl = *reinterpret_cast<const uint2*>(hlo + ho);

        if (t) mbar_wait_cl(barE, (uint32_t)((t - 1) & 1));

#pragma unroll
        for (int i = 0; i < 2; i++) {
            int lr = i * 16 + gq;
#pragma unroll
            for (int j = 0; j < 6; j++) {
                int nc = wn * 48 + j * 8 + 2 * cq;
                uint32_t a = rbase + (uint32_t)lr * 384 + (uint32_t)nc * 4;
                stc64(a,           acc[i][j][0], acc[i][j][1]);
                stc64(a + 8 * 384, acc[i][j][2], acc[i][j][3]);
            }
        }
        __syncwarp();
        if (lane == 0) mbar_arrive_rem(rfull);

        mbar_wait_cl(barF, (uint32_t)(t & 1));

        {
            float4 pr = make_float4(0.f, 0.f, 0.f, 0.f), pz = pr, pn = pr;
#pragma unroll
            for (int s = 0; s < KS; s++) {
                const char* base = smem + PRECV + s * 12288 + grl * 384;
                float4 a  = *reinterpret_cast<const float4*>(base + gc * 4);
                float4 bz = *reinterpret_cast<const float4*>(base + (32 + gc) * 4);
                float4 cn = *reinterpret_cast<const float4*>(base + (64 + gc) * 4);
                pr.x += a.x;  pr.y += a.y;  pr.z += a.z;  pr.w += a.w;
                pz.x += bz.x; pz.y += bz.y; pz.z += bz.z; pz.w += bz.w;
                pn.x += cn.x; pn.y += cn.y; pn.z += cn.z; pn.w += cn.w;
            }
            float2 hh0 = __half22float2(*reinterpret_cast<__half2*>(&rh.x));
            float2 hh1 = __half22float2(*reinterpret_cast<__half2*>(&rh.y));
            float2 hl0 = __half22float2(*reinterpret_cast<__half2*>(&rl.x));
            float2 hl1 = __half22float2(*reinterpret_cast<__half2*>(&rl.y));
            float hold[4] = { hh0.x + hl0.x, hh0.y + hl0.y, hh1.x + hl1.x, hh1.y + hl1.y };
            float hgr[4] = { pr.x, pr.y, pr.z, pr.w };
            float hgz[4] = { pz.x, pz.y, pz.z, pz.w };
            float hgn[4] = { pn.x, pn.y, pn.z, pn.w };
            float igrv[4] = { igr.x, igr.y, igr.z, igr.w };
            float igzv[4] = { igz.x, igz.y, igz.z, igz.w };
            float ignv[4] = { ign.x, ign.y, ign.z, ign.w };
            float bnvv[4] = { bnv.x, bnv.y, bnv.z, bnv.w };
            __half nhi[4], nlo[4];
#pragma unroll
            for (int q = 0; q < 4; q++) {
                float r = 1.0f / (1.0f + expf(-(igrv[q] + hgr[q])));
                float z = 1.0f / (1.0f + expf(-(igzv[q] + hgz[q])));
                float nn = tanhf(ignv[q] + r * (hgn[q] + bnvv[q]));
                float hnew = nn + z * (hold[q] - nn);
                hsplit(hnew, nhi[q], nlo[q]);
            }
            uint2 wh, wl;
            __half2 t0 = __halves2half2(nhi[0], nhi[1]);
            __half2 t1 = __halves2half2(nhi[2], nhi[3]);
            __half2 t2 = __halves2half2(nlo[0], nlo[1]);
            __half2 t3 = __halves2half2(nlo[2], nlo[3]);
            wh.x = *reinterpret_cast<uint32_t*>(&t0); wh.y = *reinterpret_cast<uint32_t*>(&t1);
            wl.x = *reinterpret_cast<uint32_t*>(&t2); wl.y = *reinterpret_cast<uint32_t*>(&t3);
            *reinterpret_cast<uint2*>(&g_h_hi[(t + 1) & 1][ho]) = wh;
            *reinterpret_cast<uint2*>(&g_h_lo[(t + 1) & 1][ho]) = wl;
        }
        __syncthreads();
        if (tid < 4) mbar_arrive_rem(rempty);
        if (tid == 0) rel_st(&g_Hf[nt][ks][0], (unsigned)(t + 1));
    }
    asm volatile("barrier.cluster.arrive.aligned;" ::: "memory");
    asm volatile("barrier.cluster.wait.aligned;" ::: "memory");
}

__global__ void out_kernel(const float* __restrict__ w_out,
                           const float* __restrict__ b_out,
                           float* __restrict__ out) {
    __shared__ float red[256];
    int b = blockIdx.x;
    float s = 0.0f;
    for (int j = threadIdx.x; j < H_; j += blockDim.x) {
        uint32_t ho = hoff(b, j);
        float h = __half2float(g_h_hi[0][ho]) + __half2float(g_h_lo[0][ho]);
        s += h * w_out[j];
    }
    red[threadIdx.x] = s;
    __syncthreads();
    for (int off = 128; off > 0; off >>= 1) {
        if (threadIdx.x < off) red[threadIdx.x] += red[threadIdx.x + off];
        __syncthreads();
    }
    if (threadIdx.x == 0) out[b] = red[0] + b_out[0];
}

extern "C" void kernel_launch(void* const* d_in, const int* in_sizes, int n_in,
                              void* d_out, int out_size) {
    const float* x     = (const float*)d_in[0];
    const float* w_ih  = (const float*)d_in[1];
    const float* w_hh  = (const float*)d_in[2];
    const float* b     = (const float*)d_in[3];
    const float* bn    = (const float*)d_in[4];
    const float* w_out = (const float*)d_in[5];
    const float* b_out = (const float*)d_in[6];
    float* out = (float*)d_out;

    cudaFuncSetAttribute(ig_gemm, cudaFuncAttributeMaxDynamicSharedMemorySize, I_SMEM);
    cudaFuncSetAttribute(gru_persist, cudaFuncAttributeMaxDynamicSharedMemorySize, R_SMEM);

    init_kernel<<<128, 256>>>();
    size_t nsplit = (size_t)G_ * H_ + (size_t)G_ * D_;
    split_w<<<(unsigned)((nsplit + 255) / 256), 256>>>(w_hh, w_ih);
    split_x<<<(unsigned)(((size_t)B_ * T_ * D_ / 2 + 255) / 256), 256>>>(x);

    dim3 gig(IGNT, T_ / TG);
    ig_gemm<<<gig, 256, I_SMEM>>>(b);

    gru_persist<<<NB, 256, R_SMEM>>>(bn);

    out_kernel<<<B_, 256>>>(w_out, b_out, out);
}

// round 12
// speedup vs baseline: 1.2548x; 1.2548x over previous
#include <cuda_runtime.h>
#include <cuda_fp16.h>
#include <cstdint>

constexpr int B_ = 128;
constexpr int T_ = 1024;
constexpr int D_ = 512;
constexpr int H_ = 1024;
constexpr int G_ = 3 * H_;

constexpr int NT = 32;
constexpr int KS = 4;
constexpr int NB = NT * KS;           // 128

constexpr int IGN  = 64;
constexpr int IGNT = G_ / IGN;
constexpr int TG   = 4;

// gru smem: W 2x48KB | A 4x16KB (h_hi chunks) | PRECV 48KB
constexpr int R_WH = 0;
constexpr int R_WL = 49152;
constexpr int AB   = 98304;
constexpr int PRECV = 163840;
constexpr int R_SMEM = 212992;

constexpr int I_WH = 0;
constexpr int I_WL = 64 * 64 * 16;
constexpr int I_XH = 2 * 64 * 64 * 16;
constexpr int I_XL = I_XH + 128 * 16 * 16;
constexpr int I_SMEM = I_XL + 128 * 16 * 16;

__device__ __align__(128) __half g_x_hi[(size_t)B_ * T_ * D_];
__device__ __align__(128) __half g_x_lo[(size_t)B_ * T_ * D_];
__device__ __align__(128) __half g_whh_hi[(size_t)G_ * H_];
__device__ __align__(128) __half g_whh_lo[(size_t)G_ * H_];
__device__ __align__(128) __half g_wih_hi[(size_t)G_ * D_];
__device__ __align__(128) __half g_wih_lo[(size_t)G_ * D_];
__device__ float g_IG[(size_t)T_ * B_ * G_];
__device__ __align__(128) __half g_h_hi[2][B_ * H_];
__device__ __align__(128) __half g_h_lo[2][B_ * H_];     // gating-only (state exactness)
__device__ unsigned int g_Hf[NT][KS][32];

__device__ __forceinline__ uint32_t smem_u32(const void* p) {
    uint32_t a;
    asm("{ .reg .u64 t; cvta.to.shared.u64 t, %1; cvt.u32.u64 %0, t; }" : "=r"(a) : "l"(p));
    return a;
}
__device__ __forceinline__ void ldm4(uint32_t* r, uint32_t a) {
    asm volatile("ldmatrix.sync.aligned.m8n8.x4.shared.b16 {%0,%1,%2,%3}, [%4];"
                 : "=r"(r[0]), "=r"(r[1]), "=r"(r[2]), "=r"(r[3]) : "r"(a));
}
__device__ __forceinline__ void mma_f16(float* d, const uint32_t* a, uint32_t b0, uint32_t b1) {
    asm volatile(
        "mma.sync.aligned.m16n8k16.row.col.f32.f16.f16.f32 "
        "{%0,%1,%2,%3},{%4,%5,%6,%7},{%8,%9},{%0,%1,%2,%3};"
        : "+f"(d[0]), "+f"(d[1]), "+f"(d[2]), "+f"(d[3])
        : "r"(a[0]), "r"(a[1]), "r"(a[2]), "r"(a[3]), "r"(b0), "r"(b1));
}
__device__ __forceinline__ void cpa16(uint32_t s, const void* g) {
    asm volatile("cp.async.cg.shared.global [%0], [%1], 16;" :: "r"(s), "l"(g));
}
__device__ __forceinline__ void cp_commit() { asm volatile("cp.async.commit_group;" ::: "memory"); }
__device__ __forceinline__ void cp_wait0()  { asm volatile("cp.async.wait_group 0;" ::: "memory"); }
__device__ __forceinline__ void hsplit(float f, __half& hi, __half& lo) {
    hi = __float2half_rn(f);
    lo = __float2half_rn(f - __half2float(hi));
}
__device__ __forceinline__ void poll_ge(const unsigned int* p, unsigned int v) {
    unsigned int x;
    do {
        asm volatile("ld.acquire.gpu.global.u32 %0, [%1];" : "=r"(x) : "l"(p) : "memory");
    } while (x < v);
}
__device__ __forceinline__ void rel_st(unsigned int* p, unsigned int v) {
    asm volatile("st.release.gpu.global.u32 [%0], %1;" :: "l"(p), "r"(v) : "memory");
}
__device__ __forceinline__ void mbar_init(uint32_t a, uint32_t cnt) {
    asm volatile("mbarrier.init.shared.b64 [%0], %1;" :: "r"(a), "r"(cnt) : "memory");
}
__device__ __forceinline__ void mbar_expect(uint32_t a, uint32_t bytes) {
    asm volatile("mbarrier.arrive.expect_tx.shared.b64 _, [%0], %1;" :: "r"(a), "r"(bytes) : "memory");
}
__device__ __forceinline__ void mbar_wait(uint32_t a, uint32_t parity) {
    asm volatile(
        "{\n\t.reg .pred P;\n\tLAB_%=:\n\t"
        "mbarrier.try_wait.parity.shared.b64 P, [%0], %1;\n\t"
        "@!P bra LAB_%=;\n\t}"
        :: "r"(a), "r"(parity) : "memory");
}
__device__ __forceinline__ void bulk_g2s(uint32_t smem, const void* g, uint32_t bytes, uint32_t mbar) {
    asm volatile(
        "cp.async.bulk.shared::cluster.global.mbarrier::complete_tx::bytes [%0], [%1], %2, [%3];"
        :: "r"(smem), "l"(g), "r"(bytes), "r"(mbar) : "memory");
}
__device__ __forceinline__ uint32_t mapa_u32(uint32_t laddr, uint32_t rank) {
    uint32_t r;
    asm("mapa.shared::cluster.u32 %0, %1, %2;" : "=r"(r) : "r"(laddr), "r"(rank));
    return r;
}
__device__ __forceinline__ void stc64(uint32_t a, float x, float y) {
    asm volatile("{ .reg .b64 v; mov.b64 v, {%1,%2}; st.shared::cluster.b64 [%0], v; }"
                 :: "r"(a), "f"(x), "f"(y) : "memory");
}
#define CARR()  asm volatile("barrier.cluster.arrive.aligned;" ::: "memory")
#define CWAIT() asm volatile("barrier.cluster.wait.aligned;" ::: "memory")

__device__ __forceinline__ uint32_t hoff(int b, int j) {
    return ((uint32_t)(j >> 6) << 13) + ((uint32_t)b << 6)
         + ((uint32_t)(((j >> 3) & 7) ^ (b & 7)) << 3) + (uint32_t)(j & 7);
}

__global__ void init_kernel() {
    unsigned idx = blockIdx.x * blockDim.x + threadIdx.x;
    for (unsigned i = idx; i < (unsigned)(NT * KS * 32); i += gridDim.x * blockDim.x)
        (&g_Hf[0][0][0])[i] = 0u;
    for (unsigned i = idx; i < (unsigned)(B_ * H_); i += gridDim.x * blockDim.x) {
        g_h_hi[0][i] = __float2half(0.0f);
        g_h_lo[0][i] = __float2half(0.0f);
    }
}
__global__ void split_w(const float* __restrict__ whh, const float* __restrict__ wih) {
    size_t i = (size_t)blockIdx.x * blockDim.x + threadIdx.x;
    size_t nhh = (size_t)G_ * H_;
    if (i < nhh) {
        __half hi, lo; hsplit(whh[i], hi, lo);
        int ghrow = (int)(i >> 10), k = (int)(i & 1023);
        int gate = ghrow >> 10, hrow = ghrow & 1023;
        int nt = hrow >> 5, nc = gate * 32 + (hrow & 31);
        int ks = k >> 8, kk = k & 255;
        int swz = ((kk >> 3) & 7) ^ (nc & 7);
        size_t dst = (size_t)(nt * KS + ks) * 24576 + (kk >> 6) * 6144 + nc * 64 + swz * 8 + (kk & 7);
        g_whh_hi[dst] = hi; g_whh_lo[dst] = lo;
    } else if (i < nhh + (size_t)G_ * D_) {
        size_t j = i - nhh;
        __half hi, lo; hsplit(wih[j], hi, lo);
        g_wih_hi[j] = hi; g_wih_lo[j] = lo;
    }
}
__global__ void split_x(const float* __restrict__ x) {
    size_t i = (size_t)blockIdx.x * blockDim.x + threadIdx.x;
    size_t n2 = (size_t)B_ * T_ * D_ / 2;
    if (i < n2) {
        float2 v = reinterpret_cast<const float2*>(x)[i];
        __half h0, l0, h1, l1;
        hsplit(v.x, h0, l0); hsplit(v.y, h1, l1);
        reinterpret_cast<__half2*>(g_x_hi)[i] = __halves2half2(h0, h1);
        reinterpret_cast<__half2*>(g_x_lo)[i] = __halves2half2(l0, l1);
    }
}

// IG GEMM (proven, unchanged)
__global__ __launch_bounds__(256, 1) void ig_gemm(const float* __restrict__ bias) {
    extern __shared__ __align__(1024) char smem[];
    const uint32_t sb = smem_u32(smem);
    const int tid = threadIdx.x;
    const int lane = tid & 31, warp = tid >> 5;
    const int wm = warp >> 1, wn = warp & 1;
    const int g8 = lane >> 3, r8 = lane & 7;
    const int gq = lane >> 2, cq = lane & 3;
    const int n0 = blockIdx.x * IGN;

    int rowA[2], rowB[2];
    rowA[0] = wm * 32 + r8 + (g8 & 1) * 8; rowA[1] = rowA[0] + 16;
    rowB[0] = wn * 32 + r8 + (g8 >> 1) * 8; rowB[1] = rowB[0] + 16;
    const int cbA = g8 >> 1, cbB = g8 & 1;

    for (int idx = tid; idx < 64 * 64; idx += 256) {
        int row = idx >> 6, c = idx & 63;
        size_t src = (size_t)(n0 + row) * D_ + c * 8;
        uint32_t off = ((row * 64 + (c ^ (row & 7))) << 4);
        cpa16(sb + I_WH + off, g_wih_hi + src);
        cpa16(sb + I_WL + off, g_wih_lo + src);
    }
    cp_commit(); cp_wait0();
    __syncthreads();

    for (int tt = 0; tt < TG; tt++) {
        const int t = blockIdx.y * TG + tt;
        float acc[2][4][4];
#pragma unroll
        for (int i = 0; i < 2; i++)
#pragma unroll
            for (int j = 0; j < 4; j++)
#pragma unroll
                for (int q = 0; q < 4; q++) acc[i][j][q] = 0.0f;

        for (int kc = 0; kc < 4; kc++) {
            __syncthreads();
            for (int idx = tid; idx < 128 * 16; idx += 256) {
                int row = idx >> 4, c = idx & 15;
                size_t src = ((size_t)row * T_ + t) * D_ + kc * 128 + c * 8;
                uint32_t off = ((row * 16 + (c ^ (row & 7))) << 4);
                cpa16(sb + I_XH + off, g_x_hi + src);
                cpa16(sb + I_XL + off, g_x_lo + src);
            }
            cp_commit(); cp_wait0();
            __syncthreads();

#pragma unroll
            for (int kk = 0; kk < 8; kk++) {
                const int kk2 = kk * 2;
                uint32_t ah[2][4], al[2][4];
#pragma unroll
                for (int i = 0; i < 2; i++) {
                    uint32_t off = ((rowA[i] * 16 + ((kk2 + cbA) ^ (rowA[i] & 7))) << 4);
                    ldm4(ah[i], sb + I_XH + off);
                    ldm4(al[i], sb + I_XL + off);
                }
                const int kkc = kc * 16 + kk2;
                uint32_t bh[2][4], bl[2][4];
#pragma unroll
                for (int j = 0; j < 2; j++) {
                    uint32_t off = ((rowB[j] * 64 + ((kkc + cbB) ^ (rowB[j] & 7))) << 4);
                    ldm4(bh[j], sb + I_WH + off);
                    ldm4(bl[j], sb + I_WL + off);
                }
#pragma unroll
                for (int i = 0; i < 2; i++)
#pragma unroll
                    for (int j = 0; j < 2; j++) {
                        mma_f16(acc[i][2 * j],     ah[i], bh[j][0], bh[j][1]);
                        mma_f16(acc[i][2 * j + 1], ah[i], bh[j][2], bh[j][3]);
                        mma_f16(acc[i][2 * j],     ah[i], bl[j][0], bl[j][1]);
                        mma_f16(acc[i][2 * j + 1], ah[i], bl[j][2], bl[j][3]);
                        mma_f16(acc[i][2 * j],     al[i], bh[j][0], bh[j][1]);
                        mma_f16(acc[i][2 * j + 1], al[i], bh[j][2], bh[j][3]);
                    }
            }
        }

#pragma unroll
        for (int i = 0; i < 2; i++)
#pragma unroll
            for (int j = 0; j < 4; j++) {
                int row = wm * 32 + i * 16 + gq;
                int gcol = n0 + wn * 32 + j * 8 + 2 * cq;
                float b0 = __ldg(&bias[gcol]), b1 = __ldg(&bias[gcol + 1]);
                size_t o0 = ((size_t)t * B_ + row) * G_ + gcol;
                *reinterpret_cast<float2*>(&g_IG[o0]) =
                    make_float2(acc[i][j][0] + b0, acc[i][j][1] + b1);
                *reinterpret_cast<float2*>(&g_IG[o0 + (size_t)8 * G_]) =
                    make_float2(acc[i][j][2] + b0, acc[i][j][3] + b1);
            }
    }
}

// ---------------------------------------------------------------------------
// Persistent GRU recurrence (round-9 protocol): cluster-of-4, DSMEM exchange.
// h_hi-only MMA input (2-term); exact fp32 state (hi+lo) kept for gating.
// 4 resident h chunk buffers -> all 4 bulk copies issued upfront.
// ---------------------------------------------------------------------------
__global__ __launch_bounds__(256, 1) __cluster_dims__(4, 1, 1)
void gru_persist(const float* __restrict__ bn) {
    extern __shared__ __align__(1024) char smem[];
    __shared__ __align__(16) unsigned long long s_bar[5];   // 0-3 chunks, 4 W
    const uint32_t sb = smem_u32(smem);
    uint32_t barC[4];
#pragma unroll
    for (int c = 0; c < 4; c++) barC[c] = smem_u32(&s_bar[c]);
    const uint32_t barW = smem_u32(&s_bar[4]);

    const int tid = threadIdx.x;
    const int lane = tid & 31, warp = tid >> 5;
    const int wm = warp >> 1, wn = warp & 1;
    const int g8 = lane >> 3, r8 = lane & 7;
    const int gq = lane >> 2, cq = lane & 3;

    uint32_t rank;
    asm("mov.u32 %0, %%cluster_ctarank;" : "=r"(rank));
    const int ks = (int)rank;
    const int nt = blockIdx.x >> 2;
    const int slab = nt * KS + ks;

    int rowA[2], rowB[3];
    rowA[0] = wm * 32 + r8 + (g8 & 1) * 8; rowA[1] = rowA[0] + 16;
    rowB[0] = wn * 48 + r8 + (g8 >> 1) * 8; rowB[1] = rowB[0] + 16; rowB[2] = rowB[0] + 32;
    const int cbA = g8 >> 1, cbB = g8 & 1;

    if (tid == 0) {
#pragma unroll
        for (int c = 0; c < 4; c++) mbar_init(barC[c], 1);
        mbar_init(barW, 1);
    }
    __syncthreads();
    if (tid == 0) {
        mbar_expect(barW, 98304);
        bulk_g2s(sb + R_WH, g_whh_hi + (size_t)slab * 24576, 49152, barW);
        bulk_g2s(sb + R_WL, g_whh_lo + (size_t)slab * 24576, 49152, barW);
    }
    mbar_wait(barW, 0);
    __syncthreads();

    const int grl = tid >> 3;
    const int gc  = (tid & 7) * 4;
    const int hc  = nt * 32 + gc;
    const uint32_t rbase = mapa_u32(sb + PRECV + (uint32_t)ks * 12288, (uint32_t)wm);

    for (int t = 0; t < T_; t++) {
        // staging deps: h cols for k-slice [ks*256,+256) ready at step t
        if (tid < 32) poll_ge(&g_Hf[ks * 8 + (tid >> 2)][tid & 3][0], (unsigned)t);
        __syncthreads();

        const __half* hhi = g_h_hi[t & 1];
        const __half* hlo = g_h_lo[t & 1];

        // stage all 4 h_hi chunks (16KB each, independent buffers)
        if (tid == 0) {
#pragma unroll
            for (int c = 0; c < 4; c++) {
                mbar_expect(barC[c], 16384);
                bulk_g2s(sb + AB + c * 16384, hhi + (size_t)(ks * 4 + c) * 8192, 16384, barC[c]);
            }
        }

        float acc[2][6][4];
#pragma unroll
        for (int i = 0; i < 2; i++)
#pragma unroll
            for (int j = 0; j < 6; j++)
#pragma unroll
                for (int q = 0; q < 4; q++) acc[i][j][q] = 0.0f;

#pragma unroll
        for (int kc = 0; kc < 4; kc++) {
            const uint32_t buf = sb + AB + kc * 16384;
            mbar_wait(barC[kc], (uint32_t)(t & 1));
#pragma unroll
            for (int kk = 0; kk < 4; kk++) {
                const int kk2 = kk * 2;
                uint32_t ah[2][4];
#pragma unroll
                for (int i = 0; i < 2; i++) {
                    int c = kk2 + cbA;
                    uint32_t off = ((uint32_t)rowA[i] << 7) + ((uint32_t)(c ^ (rowA[i] & 7)) << 4);
                    ldm4(ah[i], buf + off);
                }
                uint32_t bh[3][4], bl[3][4];
#pragma unroll
                for (int j = 0; j < 3; j++) {
                    int cg = kc * 8 + kk2 + cbB;
                    uint32_t off = (uint32_t)kc * 12288 + ((uint32_t)rowB[j] << 7)
                                 + ((uint32_t)((cg & 7) ^ (rowB[j] & 7)) << 4);
                    ldm4(bh[j], sb + R_WH + off);
                    ldm4(bl[j], sb + R_WL + off);
                }
#pragma unroll
                for (int i = 0; i < 2; i++)
#pragma unroll
                    for (int j = 0; j < 3; j++) {
                        mma_f16(acc[i][2 * j],     ah[i], bh[j][0], bh[j][1]);
                        mma_f16(acc[i][2 * j + 1], ah[i], bh[j][2], bh[j][3]);
                        mma_f16(acc[i][2 * j],     ah[i], bl[j][0], bl[j][1]);
                        mma_f16(acc[i][2 * j + 1], ah[i], bl[j][2], bl[j][3]);
                    }
            }
        }

        // prefetch gating operands (independent of partials)
        const int grow = ks * 32 + grl;
        const float* ig_t = g_IG + ((size_t)t * B_ + grow) * G_;
        float4 igr = *reinterpret_cast<const float4*>(ig_t + hc);
        float4 igz = *reinterpret_cast<const float4*>(ig_t + H_ + hc);
        float4 ign = *reinterpret_cast<const float4*>(ig_t + 2 * H_ + hc);
        float4 bnv = *reinterpret_cast<const float4*>(bn + hc);
        uint32_t ho = hoff(grow, hc);
        uint2 rh = *reinterpret_cast<const uint2*>(hhi + ho);
        uint2 rl = *reinterpret_cast<const uint2*>(hlo + ho);

        // peers must be done reading PRECV(t-1)
        if (t) CWAIT();

        // push partials: warp (wm,wn) -> rank wm, slab = own ks
#pragma unroll
        for (int i = 0; i < 2; i++) {
            int lr = i * 16 + gq;
#pragma unroll
            for (int j = 0; j < 6; j++) {
                int nc = wn * 48 + j * 8 + 2 * cq;
                uint32_t a = rbase + (uint32_t)lr * 384 + (uint32_t)nc * 4;
                stc64(a,           acc[i][j][0], acc[i][j][1]);
                stc64(a + 8 * 384, acc[i][j][2], acc[i][j][3]);
            }
        }
        CARR(); CWAIT();   // pushes visible cluster-wide

        // gating
        {
            float4 pr = make_float4(0.f, 0.f, 0.f, 0.f), pz = pr, pn = pr;
#pragma unroll
            for (int s = 0; s < KS; s++) {
                const char* base = smem + PRECV + s * 12288 + grl * 384;
                float4 a  = *reinterpret_cast<const float4*>(base + gc * 4);
                float4 bz = *reinterpret_cast<const float4*>(base + (32 + gc) * 4);
                float4 cn = *reinterpret_cast<const float4*>(base + (64 + gc) * 4);
                pr.x += a.x;  pr.y += a.y;  pr.z += a.z;  pr.w += a.w;
                pz.x += bz.x; pz.y += bz.y; pz.z += bz.z; pz.w += bz.w;
                pn.x += cn.x; pn.y += cn.y; pn.z += cn.z; pn.w += cn.w;
            }
            float2 hh0 = __half22float2(*reinterpret_cast<__half2*>(&rh.x));
            float2 hh1 = __half22float2(*reinterpret_cast<__half2*>(&rh.y));
            float2 hl0 = __half22float2(*reinterpret_cast<__half2*>(&rl.x));
            float2 hl1 = __half22float2(*reinterpret_cast<__half2*>(&rl.y));
            float hold[4] = { hh0.x + hl0.x, hh0.y + hl0.y, hh1.x + hl1.x, hh1.y + hl1.y };
            float hgr[4] = { pr.x, pr.y, pr.z, pr.w };
            float hgz[4] = { pz.x, pz.y, pz.z, pz.w };
            float hgn[4] = { pn.x, pn.y, pn.z, pn.w };
            float igrv[4] = { igr.x, igr.y, igr.z, igr.w };
            float igzv[4] = { igz.x, igz.y, igz.z, igz.w };
            float ignv[4] = { ign.x, ign.y, ign.z, ign.w };
            float bnvv[4] = { bnv.x, bnv.y, bnv.z, bnv.w };
            __half nhi[4], nlo[4];
#pragma unroll
            for (int q = 0; q < 4; q++) {
                float r = 1.0f / (1.0f + expf(-(igrv[q] + hgr[q])));
                float z = 1.0f / (1.0f + expf(-(igzv[q] + hgz[q])));
                float nn = tanhf(ignv[q] + r * (hgn[q] + bnvv[q]));
                float hnew = nn + z * (hold[q] - nn);
                hsplit(hnew, nhi[q], nlo[q]);
            }
            uint2 wh, wl;
            __half2 t0 = __halves2half2(nhi[0], nhi[1]);
            __half2 t1 = __halves2half2(nhi[2], nhi[3]);
            __half2 t2 = __halves2half2(nlo[0], nlo[1]);
            __half2 t3 = __halves2half2(nlo[2], nlo[3]);
            wh.x = *reinterpret_cast<uint32_t*>(&t0); wh.y = *reinterpret_cast<uint32_t*>(&t1);
            wl.x = *reinterpret_cast<uint32_t*>(&t2); wl.y = *reinterpret_cast<uint32_t*>(&t3);
            *reinterpret_cast<uint2*>(&g_h_hi[(t + 1) & 1][ho]) = wh;
            *reinterpret_cast<uint2*>(&g_h_lo[(t + 1) & 1][ho]) = wl;
        }
        __syncthreads();
        if (tid == 0) rel_st(&g_Hf[nt][ks][0], (unsigned)(t + 1));
        CARR();            // gate-done; waited at top of next step's push phase
    }
    CWAIT();
}

__global__ void out_kernel(const float* __restrict__ w_out,
                           const float* __restrict__ b_out,
                           float* __restrict__ out) {
    __shared__ float red[256];
    int b = blockIdx.x;
    float s = 0.0f;
    for (int j = threadIdx.x; j < H_; j += blockDim.x) {
        uint32_t ho = hoff(b, j);
        float h = __half2float(g_h_hi[0][ho]) + __half2float(g_h_lo[0][ho]);
        s += h * w_out[j];
    }
    red[threadIdx.x] = s;
    __syncthreads();
    for (int off = 128; off > 0; off >>= 1) {
        if (threadIdx.x < off) red[threadIdx.x] += red[threadIdx.x + off];
        __syncthreads();
    }
    if (threadIdx.x == 0) out[b] = red[0] + b_out[0];
}

extern "C" void kernel_launch(void* const* d_in, const int* in_sizes, int n_in,
                              void* d_out, int out_size) {
    const float* x     = (const float*)d_in[0];
    const float* w_ih  = (const float*)d_in[1];
    const float* w_hh  = (const float*)d_in[2];
    const float* b     = (const float*)d_in[3];
    const float* bn    = (const float*)d_in[4];
    const float* w_out = (const float*)d_in[5];
    const float* b_out = (const float*)d_in[6];
    float* out = (float*)d_out;

    cudaFuncSetAttribute(ig_gemm, cudaFuncAttributeMaxDynamicSharedMemorySize, I_SMEM);
    cudaFuncSetAttribute(gru_persist, cudaFuncAttributeMaxDynamicSharedMemorySize, R_SMEM);

    init_kernel<<<128, 256>>>();
    size_t nsplit = (size_t)G_ * H_ + (size_t)G_ * D_;
    split_w<<<(unsigned)((nsplit + 255) / 256), 256>>>(w_hh, w_ih);
    split_x<<<(unsigned)(((size_t)B_ * T_ * D_ / 2 + 255) / 256), 256>>>(x);

    dim3 gig(IGNT, T_ / TG);
    ig_gemm<<<gig, 256, I_SMEM>>>(b);

    gru_persist<<<NB, 256, R_SMEM>>>(bn);

    out_kernel<<<B_, 256>>>(w_out, b_out, out);
}